// round 2
// baseline (speedup 1.0000x reference)
#include <cuda_runtime.h>
#include <float.h>
#include <math.h>

#define NB 32
#define NL 2048
#define NC 1024
#define KSEL 20
#define GNEPS 1e-5f
#define NLT 16   // number of 128-row L tiles per batch

// ---------------- scratch (device globals; no allocations allowed) ----------
__device__ float g_pmax[NLT * NB * NC];
__device__ float g_psum[NLT * NB * NC];
__device__ float g_xA[NB * NC];
__device__ float g_xmean[NB * NC];
__device__ float g_tM[NB * NC];
__device__ float g_tA[NB * NC];
__device__ float g_gn1[NB * NC];
__device__ float g_gn2[NB * NC];
__device__ float g_v[NB * NC];
__device__ float g_u[NB * NC];
__device__ float g_s[NB * NL];
__device__ int   g_top[NB * KSEL];
__device__ float g_xg[NB * KSEL * NC];
__device__ float g_y[NB * KSEL * NC];

// ---------------------------------------------------------------------------
// GEMM1: x[b,l,d] = sum_c x0[b,l,c]*W[d,c] + bias[d], fused column max & sum
// over the 128 l-rows of this tile. Writes per-(ltile) partials (deterministic,
// no atomics). 128x128x8 tiling, 8x8 per thread, 256 threads.
// ---------------------------------------------------------------------------
__global__ void __launch_bounds__(256, 2)
gemm1_maxsum(const float* __restrict__ X0, const float* __restrict__ W,
             const float* __restrict__ bias)
{
    const int ltile = blockIdx.x;   // 0..15
    const int dtile = blockIdx.y;   // 0..7
    const int b     = blockIdx.z;   // 0..31

    const float* Aptr = X0 + ((size_t)b * NL + (size_t)ltile * 128) * NC;
    const float* Bptr = W + (size_t)dtile * 128 * NC;

    __shared__ float As[8][128];
    __shared__ float Bs[8][128];
    __shared__ float sred[16][128];

    const int tid  = threadIdx.x;
    const int tx   = tid & 15;
    const int ty   = tid >> 4;
    const int lrow = tid >> 1;        // 0..127
    const int lk4  = (tid & 1) * 4;   // 0 or 4

    float acc[8][8];
#pragma unroll
    for (int i = 0; i < 8; i++)
#pragma unroll
        for (int j = 0; j < 8; j++) acc[i][j] = 0.f;

    float4 a4 = *(const float4*)(Aptr + (size_t)lrow * NC + lk4);
    float4 b4 = *(const float4*)(Bptr + (size_t)lrow * NC + lk4);

    for (int k0 = 0; k0 < NC; k0 += 8) {
        __syncthreads();
        As[lk4 + 0][lrow] = a4.x; As[lk4 + 1][lrow] = a4.y;
        As[lk4 + 2][lrow] = a4.z; As[lk4 + 3][lrow] = a4.w;
        Bs[lk4 + 0][lrow] = b4.x; Bs[lk4 + 1][lrow] = b4.y;
        Bs[lk4 + 2][lrow] = b4.z; Bs[lk4 + 3][lrow] = b4.w;
        __syncthreads();
        if (k0 + 8 < NC) {
            a4 = *(const float4*)(Aptr + (size_t)lrow * NC + k0 + 8 + lk4);
            b4 = *(const float4*)(Bptr + (size_t)lrow * NC + k0 + 8 + lk4);
        }
#pragma unroll
        for (int kk = 0; kk < 8; kk++) {
            float ra[8], rb[8];
            *(float4*)(ra)     = *(const float4*)(&As[kk][ty * 8]);
            *(float4*)(ra + 4) = *(const float4*)(&As[kk][ty * 8 + 4]);
            *(float4*)(rb)     = *(const float4*)(&Bs[kk][tx * 8]);
            *(float4*)(rb + 4) = *(const float4*)(&Bs[kk][tx * 8 + 4]);
#pragma unroll
            for (int i = 0; i < 8; i++)
#pragma unroll
                for (int j = 0; j < 8; j++)
                    acc[i][j] += ra[i] * rb[j];
        }
    }

    // Epilogue: add bias, reduce max & sum over the tile's 128 rows per column.
    float cmax[8], csum[8];
#pragma unroll
    for (int j = 0; j < 8; j++) {
        float bd = __ldg(bias + dtile * 128 + tx * 8 + j);
        float m = -FLT_MAX, s = 0.f;
#pragma unroll
        for (int i = 0; i < 8; i++) {
            float v = acc[i][j] + bd;
            m = fmaxf(m, v);
            s += v;
        }
        cmax[j] = m; csum[j] = s;
    }
#pragma unroll
    for (int j = 0; j < 8; j++) sred[ty][tx * 8 + j] = cmax[j];
    __syncthreads();
    float rm = -FLT_MAX;
    if (tid < 128) {
#pragma unroll
        for (int t = 0; t < 16; t++) rm = fmaxf(rm, sred[t][tid]);
    }
    __syncthreads();
#pragma unroll
    for (int j = 0; j < 8; j++) sred[ty][tx * 8 + j] = csum[j];
    __syncthreads();
    if (tid < 128) {
        float rs = 0.f;
#pragma unroll
        for (int t = 0; t < 16; t++) rs += sred[t][tid];
        size_t o = ((size_t)ltile * NB + b) * NC + dtile * 128 + tid;
        g_pmax[o] = rm;
        g_psum[o] = rs;
    }
}

// Reduce the 16 per-tile partials -> x_A (max) and x_mean (mean over L).
__global__ void reduce_maxsum()
{
    int idx = blockIdx.x * 256 + threadIdx.x;   // 0 .. NB*NC-1
    float m = -FLT_MAX, s = 0.f;
#pragma unroll
    for (int t = 0; t < NLT; t++) {
        m = fmaxf(m, g_pmax[(size_t)t * NB * NC + idx]);
        s += g_psum[(size_t)t * NB * NC + idx];
    }
    g_xA[idx] = m;
    g_xmean[idx] = s * (1.0f / NL);
}

// out[b,n] = sum_k A[b,k]*M[n,k] + bias[n]   (M row-major [N,K]); warp per (b,n)
__global__ void __launch_bounds__(256)
small_gemm_T(const float* __restrict__ Ain, const float* __restrict__ M,
             const float* __restrict__ bias, float* __restrict__ out)
{
    int b = blockIdx.y;
    __shared__ float sA[NC];
    int tid = threadIdx.x;
    for (int i = tid; i < NC; i += 256) sA[i] = Ain[b * NC + i];
    __syncthreads();
    int warp = tid >> 5, lane = tid & 31;
    int n = blockIdx.x * 8 + warp;
    const float4* Mr = (const float4*)(M + (size_t)n * NC);
    const float4* Ar = (const float4*)sA;
    float acc = 0.f;
#pragma unroll 4
    for (int i = lane; i < NC / 4; i += 32) {
        float4 m4 = __ldg(&Mr[i]);
        float4 a4 = Ar[i];
        acc += m4.x * a4.x + m4.y * a4.y + m4.z * a4.z + m4.w * a4.w;
    }
#pragma unroll
    for (int o = 16; o; o >>= 1) acc += __shfl_xor_sync(0xffffffffu, acc, o);
    if (lane == 0) out[b * NC + n] = acc + __ldg(bias + n);
}

// GroupNorm on [NB, NC] rows, 32 groups of 32 channels (group == one warp).
__global__ void gn_kernel(const float* __restrict__ t, const float* __restrict__ w,
                          const float* __restrict__ bb, float* __restrict__ o)
{
    int b = blockIdx.x;
    int c = threadIdx.x;  // 1024 threads
    float v = t[b * NC + c];
    float s = v;
#pragma unroll
    for (int off = 16; off; off >>= 1) s += __shfl_xor_sync(0xffffffffu, s, off);
    float mean = s * (1.f / 32.f);
    float d = v - mean;
    float q = d * d;
#pragma unroll
    for (int off = 16; off; off >>= 1) q += __shfl_xor_sync(0xffffffffu, q, off);
    float var = q * (1.f / 32.f);
    o[b * NC + c] = d * rsqrtf(var + GNEPS) * __ldg(w + c) + __ldg(bb + c);
}

// out[b,c] (+)= sum_d A[b,d]*M[d,c]   (M row-major [D,C], reduce over rows)
template <bool ACCUM>
__global__ void __launch_bounds__(256)
small_gemm_N(const float* __restrict__ Ain, const float* __restrict__ M,
             float* __restrict__ out)
{
    int b = blockIdx.y;
    int c = blockIdx.x * 256 + threadIdx.x;
    __shared__ float sA[NC];
    for (int i = threadIdx.x; i < NC; i += 256) sA[i] = Ain[b * NC + i];
    __syncthreads();
    float acc = ACCUM ? out[b * NC + c] : 0.f;
#pragma unroll 8
    for (int d = 0; d < NC; d++)
        acc += sA[d] * __ldg(M + (size_t)d * NC + c);
    out[b * NC + c] = acc;
}

// s[b,l] = x0[b,l,:] . u[b,:]   (one warp per row, u staged in smem)
__global__ void __launch_bounds__(256)
dot_kernel(const float* __restrict__ X0)
{
    int b = blockIdx.y;
    __shared__ float su[NC];
    for (int i = threadIdx.x; i < NC; i += 256) su[i] = g_u[b * NC + i];
    __syncthreads();
    int warp = threadIdx.x >> 5, lane = threadIdx.x & 31;
    int l = blockIdx.x * 8 + warp;
    const float4* xr = (const float4*)(X0 + ((size_t)b * NL + l) * NC);
    const float4* ur = (const float4*)su;
    float acc = 0.f;
#pragma unroll 4
    for (int i = lane; i < NC / 4; i += 32) {
        float4 x = __ldg(&xr[i]);
        float4 u = ur[i];
        acc += x.x * u.x + x.y * u.y + x.z * u.z + x.w * u.w;
    }
#pragma unroll
    for (int o = 16; o; o >>= 1) acc += __shfl_xor_sync(0xffffffffu, acc, o);
    if (lane == 0) g_s[b * NL + l] = acc;
}

// Iterative top-20 per batch (ties -> lowest index, matching jax top_k).
__global__ void __launch_bounds__(256) topk_kernel()
{
    int b = blockIdx.x;
    __shared__ float vals[NL];
    __shared__ float rmx[256];
    __shared__ int   rix[256];
    int tid = threadIdx.x;
    for (int i = tid; i < NL; i += 256) vals[i] = g_s[b * NL + i];
    __syncthreads();
    for (int it = 0; it < KSEL; it++) {
        float m = -FLT_MAX; int mi = 0;
        for (int i = tid; i < NL; i += 256) {
            float v = vals[i];
            if (v > m) { m = v; mi = i; }
        }
        rmx[tid] = m; rix[tid] = mi;
        __syncthreads();
        for (int st = 128; st > 0; st >>= 1) {
            if (tid < st) {
                float vo = rmx[tid + st]; int io = rix[tid + st];
                if (vo > rmx[tid] || (vo == rmx[tid] && io < rix[tid])) {
                    rmx[tid] = vo; rix[tid] = io;
                }
            }
            __syncthreads();
        }
        if (tid == 0) {
            g_top[b * KSEL + it] = rix[0];
            vals[rix[0]] = -FLT_MAX;
        }
        __syncthreads();
    }
}

// Gather the 640 selected x0 rows.
__global__ void gather_kernel(const float* __restrict__ X0)
{
    int r = blockIdx.x;          // 0..639
    int b = r / KSEL;
    int l = g_top[r];
    const float4* src = (const float4*)(X0 + ((size_t)b * NL + l) * NC);
    float4* dst = (float4*)(g_xg + (size_t)r * NC);
    dst[threadIdx.x] = src[threadIdx.x];   // 256 threads * float4
}

// out[m,n] = sum_k A[m,k]*Bw[n,k] + bias[n]; M=640, N=K=1024. 64x64x16 tiles.
__global__ void __launch_bounds__(256)
gemm2(const float* __restrict__ A, const float* __restrict__ Bw,
      const float* __restrict__ bias, float* __restrict__ out)
{
    const int mtile = blockIdx.x, ntile = blockIdx.y;
    __shared__ float As[16][64];
    __shared__ float Bs[16][64];
    int tid = threadIdx.x;
    int tx = tid & 15, ty = tid >> 4;
    const float* Ap = A + (size_t)mtile * 64 * NC;
    const float* Bp = Bw + (size_t)ntile * 64 * NC;
    int lrow = tid >> 2;          // 0..63
    int lk4  = (tid & 3) * 4;     // 0,4,8,12

    float acc[4][4];
#pragma unroll
    for (int i = 0; i < 4; i++)
#pragma unroll
        for (int j = 0; j < 4; j++) acc[i][j] = 0.f;

    float4 a4 = *(const float4*)(Ap + (size_t)lrow * NC + lk4);
    float4 b4 = *(const float4*)(Bp + (size_t)lrow * NC + lk4);

    for (int k0 = 0; k0 < NC; k0 += 16) {
        __syncthreads();
        As[lk4 + 0][lrow] = a4.x; As[lk4 + 1][lrow] = a4.y;
        As[lk4 + 2][lrow] = a4.z; As[lk4 + 3][lrow] = a4.w;
        Bs[lk4 + 0][lrow] = b4.x; Bs[lk4 + 1][lrow] = b4.y;
        Bs[lk4 + 2][lrow] = b4.z; Bs[lk4 + 3][lrow] = b4.w;
        __syncthreads();
        if (k0 + 16 < NC) {
            a4 = *(const float4*)(Ap + (size_t)lrow * NC + k0 + 16 + lk4);
            b4 = *(const float4*)(Bp + (size_t)lrow * NC + k0 + 16 + lk4);
        }
#pragma unroll
        for (int kk = 0; kk < 16; kk++) {
            float ra[4], rb[4];
            *(float4*)ra = *(const float4*)(&As[kk][ty * 4]);
            *(float4*)rb = *(const float4*)(&Bs[kk][tx * 4]);
#pragma unroll
            for (int i = 0; i < 4; i++)
#pragma unroll
                for (int j = 0; j < 4; j++)
                    acc[i][j] += ra[i] * rb[j];
        }
    }
#pragma unroll
    for (int j = 0; j < 4; j++) {
        float bd = __ldg(bias + ntile * 64 + tx * 4 + j);
#pragma unroll
        for (int i = 0; i < 4; i++)
            out[((size_t)mtile * 64 + ty * 4 + i) * NC + ntile * 64 + tx * 4 + j] =
                acc[i][j] + bd;
    }
}

// ---------------------------------------------------------------------------
static float* symf(const void* symbol)
{
    void* p = nullptr;
    cudaGetSymbolAddress(&p, symbol);
    return (float*)p;
}

extern "C" void kernel_launch(void* const* d_in, const int* in_sizes, int n_in,
                              void* d_out, int out_size)
{
    const float* x0  = (const float*)d_in[0];
    const float* W   = (const float*)d_in[1];
    const float* b   = (const float*)d_in[2];
    const float* W1  = (const float*)d_in[3];
    const float* b1  = (const float*)d_in[4];
    const float* Wm  = (const float*)d_in[5];
    const float* bm  = (const float*)d_in[6];
    const float* Wa  = (const float*)d_in[7];
    const float* ba  = (const float*)d_in[8];
    const float* g1w = (const float*)d_in[9];
    const float* g1b = (const float*)d_in[10];
    const float* g2w = (const float*)d_in[11];
    const float* g2b = (const float*)d_in[12];
    float* out = (float*)d_out;

    float* p_xmean = symf(g_xmean);
    float* p_xA    = symf(g_xA);
    float* p_tM    = symf(g_tM);
    float* p_tA    = symf(g_tA);
    float* p_gn1   = symf(g_gn1);
    float* p_gn2   = symf(g_gn2);
    float* p_v     = symf(g_v);
    float* p_u     = symf(g_u);
    float* p_xg    = symf(g_xg);
    float* p_y     = symf(g_y);

    // 1) Big GEMM (x = x0 @ W^T + b) with fused max/sum-over-L epilogue
    dim3 grid1(NLT, NC / 128, NB);
    gemm1_maxsum<<<grid1, 256>>>(x0, W, b);
    reduce_maxsum<<<(NB * NC) / 256, 256>>>();

    // 2) Pooled branches: t = pooled @ Wm^T/Wa^T + bias, then GroupNorm
    dim3 gst(NC / 8, NB);
    small_gemm_T<<<gst, 256>>>(p_xmean, Wm, bm, p_tM);
    small_gemm_T<<<gst, 256>>>(p_xA, Wa, ba, p_tA);
    gn_kernel<<<NB, 1024>>>(p_tM, g1w, g1b, p_gn1);
    gn_kernel<<<NB, 1024>>>(p_tA, g2w, g2b, p_gn2);

    // 3) v = (gn1 + gn2-branch) pushed through W1 (reduce over rows), then u = v @ W
    dim3 gsn(NC / 256, NB);
    small_gemm_N<false><<<gsn, 256>>>(p_gn1, W1, p_v);
    small_gemm_N<true ><<<gsn, 256>>>(p_gn2, W1, p_v);
    small_gemm_N<false><<<gsn, 256>>>(p_v, W, p_u);

    // 4) scores s[b,l] = x0 . u  (softmax product ordering == out1+out2 ordering)
    dim3 gdot(NL / 8, NB);
    dot_kernel<<<gdot, 256>>>(x0);

    // 5) top-20 per batch, gather selected x0 rows
    topk_kernel<<<NB, 256>>>();
    gather_kernel<<<NB * KSEL, 256>>>(x0);

    // 6) exact fp32 recompute of the two linears for the 640 selected rows
    dim3 gg2((NB * KSEL) / 64, NC / 64);
    gemm2<<<gg2, 256>>>(p_xg, W, b, p_y);
    gemm2<<<gg2, 256>>>(p_y, W1, b1, out);
}

// round 4
// speedup vs baseline: 1.7990x; 1.7990x over previous
#include <cuda_runtime.h>
#include <cuda_fp16.h>
#include <float.h>
#include <stdint.h>
#include <math.h>

#define NB 32
#define NL 2048
#define NC 1024
#define KSEL 20
#define GNEPS 1e-5f
#define NLT 16

// ---------------- scratch (device globals; no allocations allowed) ----------
__device__ __half g_Xhi[(size_t)NB * NL * NC];
__device__ __half g_Xlo[(size_t)NB * NL * NC];
__device__ __half g_Whi[NC * NC];
__device__ __half g_Wlo[NC * NC];
__device__ float g_pmax[NLT * NB * NC];
__device__ float g_psum[NLT * NB * NC];
__device__ float g_xA[NB * NC];
__device__ float g_xmean[NB * NC];
__device__ float g_tM[NB * NC];
__device__ float g_tA[NB * NC];
__device__ float g_gn1[NB * NC];
__device__ float g_gn2[NB * NC];
__device__ float g_v[NB * NC];
__device__ float g_u[NB * NC];
__device__ float g_s[NB * NL];
__device__ int   g_top[NB * KSEL];
__device__ float g_xg[NB * KSEL * NC];
__device__ float g_y[NB * KSEL * NC];

// ----------------------------- helpers --------------------------------------
__device__ __forceinline__ uint32_t smem_u32(const void* p) {
    uint32_t a;
    asm("{ .reg .u64 t; cvta.to.shared.u64 t, %1; cvt.u32.u64 %0, t; }"
        : "=r"(a) : "l"(p));
    return a;
}
#define CP_ASYNC16(dst, src) \
    asm volatile("cp.async.cg.shared.global [%0], [%1], 16;" :: "r"(dst), "l"(src) : "memory")
#define CP_COMMIT() asm volatile("cp.async.commit_group;" ::: "memory")
#define CP_WAIT2()  asm volatile("cp.async.wait_group 2;" ::: "memory")
#define MMA16816(c, a0, a1, a2, a3, b0, b1)                                \
    asm volatile("mma.sync.aligned.m16n8k16.row.col.f32.f16.f16.f32 "      \
        "{%0,%1,%2,%3}, {%4,%5,%6,%7}, {%8,%9}, {%0,%1,%2,%3};"            \
        : "+f"((c)[0]), "+f"((c)[1]), "+f"((c)[2]), "+f"((c)[3])           \
        : "r"(a0), "r"(a1), "r"(a2), "r"(a3), "r"(b0), "r"(b1))

// ---------------------- fp16 hi/lo split pre-pass ---------------------------
__global__ void split_kernel(const float* __restrict__ src,
                             __half* __restrict__ hi, __half* __restrict__ lo)
{
    size_t i = (size_t)blockIdx.x * 256 + threadIdx.x;   // float4 index
    float4 v = ((const float4*)src)[i];
    __half h0 = __float2half_rn(v.x), h1 = __float2half_rn(v.y);
    __half h2 = __float2half_rn(v.z), h3 = __float2half_rn(v.w);
    __half l0 = __float2half_rn(v.x - __half2float(h0));
    __half l1 = __float2half_rn(v.y - __half2float(h1));
    __half l2 = __float2half_rn(v.z - __half2float(h2));
    __half l3 = __float2half_rn(v.w - __half2float(h3));
    ((__half2*)hi)[i * 2 + 0] = __halves2half2(h0, h1);
    ((__half2*)hi)[i * 2 + 1] = __halves2half2(h2, h3);
    ((__half2*)lo)[i * 2 + 0] = __halves2half2(l0, l1);
    ((__half2*)lo)[i * 2 + 1] = __halves2half2(l2, l3);
}

// ---------------------------------------------------------------------------
// GEMM1: x[m,d] = sum_k x0[m,k]*W[d,k] via fp16x3 mma.sync; fused per-column
// max & sum over the CTA tile's 128 m-rows -> g_pmax/g_psum partials.
// CTA tile 128x128, 8 warps of 64x32, 4-stage cp.async pipeline, k-chunk 16.
// grid = (8 ntiles, 512 mtiles); mtile = b*16 + ltile.
// ---------------------------------------------------------------------------
#define STAGE_BYTES 16384
#define SM1_BYTES   (4 * STAGE_BYTES)

__global__ void __launch_bounds__(256, 1)
gemm1_mma(const __half* __restrict__ Xhi, const __half* __restrict__ Xlo,
          const __half* __restrict__ Whi, const __half* __restrict__ Wlo)
{
    extern __shared__ char smem[];
    const int tid = threadIdx.x;
    const int ntile = blockIdx.x, mtile = blockIdx.y;
    const int wid = tid >> 5, lane = tid & 31;
    const int wm = wid >> 2, wn = wid & 3;
    const int gr = lane >> 2, q = lane & 3;
    const uint32_t sbase = smem_u32(smem);

    // cp.async source/dest (per-thread: one 16B chunk per buffer per stage)
    const int arow = tid >> 1, aseg = tid & 1;
    const size_t gA = (size_t)(mtile * 128 + arow) * NC + aseg * 8;
    const size_t gB = (size_t)(ntile * 128 + arow) * NC + aseg * 8;
    const uint32_t dsto = arow * 32 + ((aseg * 16) ^ (((arow >> 2) & 1) * 16));

    float acc[4][4][4];
#pragma unroll
    for (int i = 0; i < 4; i++)
#pragma unroll
        for (int j = 0; j < 4; j++)
#pragma unroll
            for (int r = 0; r < 4; r++) acc[i][j][r] = 0.f;

    // fragment byte offsets (XOR-swizzled, conflict-free lds.32)
    uint32_t aoff0[4], aoff2[4], boff0[4], boff1[4];
#pragma unroll
    for (int mt = 0; mt < 4; mt++) {
        int r = wm * 64 + mt * 16 + gr;
        int f = ((r >> 2) & 1) * 16;
        aoff0[mt] = r * 32 + ((q * 4) ^ f);
        aoff2[mt] = r * 32 + ((16 + q * 4) ^ f);
    }
#pragma unroll
    for (int nt = 0; nt < 4; nt++) {
        int n = wn * 32 + nt * 8 + gr;
        int f = ((n >> 2) & 1) * 16;
        boff0[nt] = n * 32 + ((q * 4) ^ f);
        boff1[nt] = n * 32 + ((16 + q * 4) ^ f);
    }

    auto issue = [&](int s, int k0) {
        uint32_t d = sbase + s * STAGE_BYTES + dsto;
        CP_ASYNC16(d,          Xhi + gA + k0);
        CP_ASYNC16(d + 4096u,  Xlo + gA + k0);
        CP_ASYNC16(d + 8192u,  Whi + gB + k0);
        CP_ASYNC16(d + 12288u, Wlo + gB + k0);
    };

    issue(0, 0);  CP_COMMIT();
    issue(1, 16); CP_COMMIT();
    issue(2, 32); CP_COMMIT();

    for (int ks = 0; ks < 64; ks++) {
        CP_WAIT2();
        __syncthreads();
        if (ks < 61) issue((ks + 3) & 3, (ks + 3) * 16);
        CP_COMMIT();

        const char* st = smem + (ks & 3) * STAGE_BYTES;
        uint32_t Bh[4][2], Bl[4][2];
#pragma unroll
        for (int nt = 0; nt < 4; nt++) {
            Bh[nt][0] = *(const uint32_t*)(st + 8192 + boff0[nt]);
            Bh[nt][1] = *(const uint32_t*)(st + 8192 + boff1[nt]);
            Bl[nt][0] = *(const uint32_t*)(st + 12288 + boff0[nt]);
            Bl[nt][1] = *(const uint32_t*)(st + 12288 + boff1[nt]);
        }
#pragma unroll
        for (int mt = 0; mt < 4; mt++) {
            uint32_t A0 = *(const uint32_t*)(st + aoff0[mt]);
            uint32_t A1 = *(const uint32_t*)(st + aoff0[mt] + 256);
            uint32_t A2 = *(const uint32_t*)(st + aoff2[mt]);
            uint32_t A3 = *(const uint32_t*)(st + aoff2[mt] + 256);
#pragma unroll
            for (int nt = 0; nt < 4; nt++)
                MMA16816(acc[mt][nt], A0, A1, A2, A3, Bh[nt][0], Bh[nt][1]);
#pragma unroll
            for (int nt = 0; nt < 4; nt++)
                MMA16816(acc[mt][nt], A0, A1, A2, A3, Bl[nt][0], Bl[nt][1]);
            uint32_t L0 = *(const uint32_t*)(st + 4096 + aoff0[mt]);
            uint32_t L1 = *(const uint32_t*)(st + 4096 + aoff0[mt] + 256);
            uint32_t L2 = *(const uint32_t*)(st + 4096 + aoff2[mt]);
            uint32_t L3 = *(const uint32_t*)(st + 4096 + aoff2[mt] + 256);
#pragma unroll
            for (int nt = 0; nt < 4; nt++)
                MMA16816(acc[mt][nt], L0, L1, L2, L3, Bh[nt][0], Bh[nt][1]);
        }
    }

    // ---- fused epilogue: per-column max & sum over 128 rows ----
    __syncthreads();
    float* smax = (float*)smem;          // [2][128]
    float* ssum = (float*)smem + 256;    // [2][128]

    float tm[4][2], ts[4][2];
#pragma unroll
    for (int nt = 0; nt < 4; nt++)
#pragma unroll
        for (int c = 0; c < 2; c++) {
            float m = -FLT_MAX, s = 0.f;
#pragma unroll
            for (int mt = 0; mt < 4; mt++) {
                float v0 = acc[mt][nt][c];
                float v1 = acc[mt][nt][c + 2];
                m = fmaxf(m, fmaxf(v0, v1));
                s += v0 + v1;
            }
            tm[nt][c] = m; ts[nt][c] = s;
        }
#pragma unroll
    for (int o = 4; o <= 16; o <<= 1)
#pragma unroll
        for (int nt = 0; nt < 4; nt++)
#pragma unroll
            for (int c = 0; c < 2; c++) {
                tm[nt][c] = fmaxf(tm[nt][c], __shfl_xor_sync(0xffffffffu, tm[nt][c], o));
                ts[nt][c] += __shfl_xor_sync(0xffffffffu, ts[nt][c], o);
            }
    if (gr == 0) {
#pragma unroll
        for (int nt = 0; nt < 4; nt++)
#pragma unroll
            for (int c = 0; c < 2; c++) {
                int col = wn * 32 + nt * 8 + q * 2 + c;
                smax[wm * 128 + col] = tm[nt][c];
                ssum[wm * 128 + col] = ts[nt][c];
            }
    }
    __syncthreads();
    if (tid < 128) {
        float m = fmaxf(smax[tid], smax[128 + tid]);
        float s = ssum[tid] + ssum[128 + tid];
        int b = mtile >> 4, lt = mtile & 15;
        size_t o = ((size_t)lt * NB + b) * NC + ntile * 128 + tid;
        g_pmax[o] = m;
        g_psum[o] = s;
    }
}

// Reduce 16 per-tile partials -> x_A (max) and x_mean; bias folded here.
__global__ void reduce_maxsum(const float* __restrict__ bias)
{
    int idx = blockIdx.x * 256 + threadIdx.x;
    int c = idx & (NC - 1);
    float m = -FLT_MAX, s = 0.f;
#pragma unroll
    for (int t = 0; t < NLT; t++) {
        m = fmaxf(m, g_pmax[(size_t)t * NB * NC + idx]);
        s += g_psum[(size_t)t * NB * NC + idx];
    }
    float bd = __ldg(bias + c);
    g_xA[idx] = m + bd;
    g_xmean[idx] = s * (1.0f / NL) + bd;
}

// out[b,n] = sum_k A[b,k]*M[n,k] + bias[n]
__global__ void __launch_bounds__(256)
small_gemm_T(const float* __restrict__ Ain, const float* __restrict__ M,
             const float* __restrict__ bias, float* __restrict__ out)
{
    int b = blockIdx.y;
    __shared__ float sA[NC];
    int tid = threadIdx.x;
    for (int i = tid; i < NC; i += 256) sA[i] = Ain[b * NC + i];
    __syncthreads();
    int warp = tid >> 5, lane = tid & 31;
    int n = blockIdx.x * 8 + warp;
    const float4* Mr = (const float4*)(M + (size_t)n * NC);
    const float4* Ar = (const float4*)sA;
    float acc = 0.f;
#pragma unroll 4
    for (int i = lane; i < NC / 4; i += 32) {
        float4 m4 = __ldg(&Mr[i]);
        float4 a4 = Ar[i];
        acc += m4.x * a4.x + m4.y * a4.y + m4.z * a4.z + m4.w * a4.w;
    }
#pragma unroll
    for (int o = 16; o; o >>= 1) acc += __shfl_xor_sync(0xffffffffu, acc, o);
    if (lane == 0) out[b * NC + n] = acc + __ldg(bias + n);
}

// GroupNorm: 32 groups of 32 channels (group == warp)
__global__ void gn_kernel(const float* __restrict__ t, const float* __restrict__ w,
                          const float* __restrict__ bb, float* __restrict__ o)
{
    int b = blockIdx.x;
    int c = threadIdx.x;
    float v = t[b * NC + c];
    float s = v;
#pragma unroll
    for (int off = 16; off; off >>= 1) s += __shfl_xor_sync(0xffffffffu, s, off);
    float mean = s * (1.f / 32.f);
    float d = v - mean;
    float qq = d * d;
#pragma unroll
    for (int off = 16; off; off >>= 1) qq += __shfl_xor_sync(0xffffffffu, qq, off);
    float var = qq * (1.f / 32.f);
    o[b * NC + c] = d * rsqrtf(var + GNEPS) * __ldg(w + c) + __ldg(bb + c);
}

// out[b,c] (+)= sum_d A[b,d]*M[d,c]
template <bool ACCUM>
__global__ void __launch_bounds__(256)
small_gemm_N(const float* __restrict__ Ain, const float* __restrict__ M,
             float* __restrict__ out)
{
    int b = blockIdx.y;
    int c = blockIdx.x * 256 + threadIdx.x;
    __shared__ float sA[NC];
    for (int i = threadIdx.x; i < NC; i += 256) sA[i] = Ain[b * NC + i];
    __syncthreads();
    float acc = ACCUM ? out[b * NC + c] : 0.f;
#pragma unroll 8
    for (int d = 0; d < NC; d++)
        acc += sA[d] * __ldg(M + (size_t)d * NC + c);
    out[b * NC + c] = acc;
}

// s[b,l] = x0[b,l,:] . u[b,:]
__global__ void __launch_bounds__(256)
dot_kernel(const float* __restrict__ X0)
{
    int b = blockIdx.y;
    __shared__ float su[NC];
    for (int i = threadIdx.x; i < NC; i += 256) su[i] = g_u[b * NC + i];
    __syncthreads();
    int warp = threadIdx.x >> 5, lane = threadIdx.x & 31;
    int l = blockIdx.x * 8 + warp;
    const float4* xr = (const float4*)(X0 + ((size_t)b * NL + l) * NC);
    const float4* ur = (const float4*)su;
    float acc = 0.f;
#pragma unroll 4
    for (int i = lane; i < NC / 4; i += 32) {
        float4 x = __ldg(&xr[i]);
        float4 u = ur[i];
        acc += x.x * u.x + x.y * u.y + x.z * u.z + x.w * u.w;
    }
#pragma unroll
    for (int o = 16; o; o >>= 1) acc += __shfl_xor_sync(0xffffffffu, acc, o);
    if (lane == 0) g_s[b * NL + l] = acc;
}

// Iterative top-20 per batch (ties -> lowest index)
__global__ void __launch_bounds__(256) topk_kernel()
{
    int b = blockIdx.x;
    __shared__ float vals[NL];
    __shared__ float rmx[256];
    __shared__ int   rix[256];
    int tid = threadIdx.x;
    for (int i = tid; i < NL; i += 256) vals[i] = g_s[b * NL + i];
    __syncthreads();
    for (int it = 0; it < KSEL; it++) {
        float m = -FLT_MAX; int mi = 0;
        for (int i = tid; i < NL; i += 256) {
            float v = vals[i];
            if (v > m) { m = v; mi = i; }
        }
        rmx[tid] = m; rix[tid] = mi;
        __syncthreads();
        for (int st = 128; st > 0; st >>= 1) {
            if (tid < st) {
                float vo = rmx[tid + st]; int io = rix[tid + st];
                if (vo > rmx[tid] || (vo == rmx[tid] && io < rix[tid])) {
                    rmx[tid] = vo; rix[tid] = io;
                }
            }
            __syncthreads();
        }
        if (tid == 0) {
            g_top[b * KSEL + it] = rix[0];
            vals[rix[0]] = -FLT_MAX;
        }
        __syncthreads();
    }
}

__global__ void gather_kernel(const float* __restrict__ X0)
{
    int r = blockIdx.x;
    int b = r / KSEL;
    int l = g_top[r];
    const float4* src = (const float4*)(X0 + ((size_t)b * NL + l) * NC);
    float4* dst = (float4*)(g_xg + (size_t)r * NC);
    dst[threadIdx.x] = src[threadIdx.x];
}

// out[m,n] = sum_k A[m,k]*Bw[n,k] + bias[n]; exact fp32 for selected rows
__global__ void __launch_bounds__(256)
gemm2(const float* __restrict__ A, const float* __restrict__ Bw,
      const float* __restrict__ bias, float* __restrict__ out)
{
    const int mtile = blockIdx.x, ntile = blockIdx.y;
    __shared__ float As[16][64];
    __shared__ float Bs[16][64];
    int tid = threadIdx.x;
    int tx = tid & 15, ty = tid >> 4;
    const float* Ap = A + (size_t)mtile * 64 * NC;
    const float* Bp = Bw + (size_t)ntile * 64 * NC;
    int lrow = tid >> 2;
    int lk4  = (tid & 3) * 4;

    float acc[4][4];
#pragma unroll
    for (int i = 0; i < 4; i++)
#pragma unroll
        for (int j = 0; j < 4; j++) acc[i][j] = 0.f;

    float4 a4 = *(const float4*)(Ap + (size_t)lrow * NC + lk4);
    float4 b4 = *(const float4*)(Bp + (size_t)lrow * NC + lk4);

    for (int k0 = 0; k0 < NC; k0 += 16) {
        __syncthreads();
        As[lk4 + 0][lrow] = a4.x; As[lk4 + 1][lrow] = a4.y;
        As[lk4 + 2][lrow] = a4.z; As[lk4 + 3][lrow] = a4.w;
        Bs[lk4 + 0][lrow] = b4.x; Bs[lk4 + 1][lrow] = b4.y;
        Bs[lk4 + 2][lrow] = b4.z; Bs[lk4 + 3][lrow] = b4.w;
        __syncthreads();
        if (k0 + 16 < NC) {
            a4 = *(const float4*)(Ap + (size_t)lrow * NC + k0 + 16 + lk4);
            b4 = *(const float4*)(Bp + (size_t)lrow * NC + k0 + 16 + lk4);
        }
#pragma unroll
        for (int kk = 0; kk < 16; kk++) {
            float ra[4], rb[4];
            *(float4*)ra = *(const float4*)(&As[kk][ty * 4]);
            *(float4*)rb = *(const float4*)(&Bs[kk][tx * 4]);
#pragma unroll
            for (int i = 0; i < 4; i++)
#pragma unroll
                for (int j = 0; j < 4; j++)
                    acc[i][j] += ra[i] * rb[j];
        }
    }
#pragma unroll
    for (int j = 0; j < 4; j++) {
        float bd = __ldg(bias + ntile * 64 + tx * 4 + j);
#pragma unroll
        for (int i = 0; i < 4; i++)
            out[((size_t)mtile * 64 + ty * 4 + i) * NC + ntile * 64 + tx * 4 + j] =
                acc[i][j] + bd;
    }
}

// ---------------------------------------------------------------------------
static void* symp(const void* symbol)
{
    void* p = nullptr;
    cudaGetSymbolAddress(&p, symbol);
    return p;
}

extern "C" void kernel_launch(void* const* d_in, const int* in_sizes, int n_in,
                              void* d_out, int out_size)
{
    const float* x0  = (const float*)d_in[0];
    const float* W   = (const float*)d_in[1];
    const float* b   = (const float*)d_in[2];
    const float* W1  = (const float*)d_in[3];
    const float* b1  = (const float*)d_in[4];
    const float* Wm  = (const float*)d_in[5];
    const float* bm  = (const float*)d_in[6];
    const float* Wa  = (const float*)d_in[7];
    const float* ba  = (const float*)d_in[8];
    const float* g1w = (const float*)d_in[9];
    const float* g1b = (const float*)d_in[10];
    const float* g2w = (const float*)d_in[11];
    const float* g2b = (const float*)d_in[12];
    float* out = (float*)d_out;

    __half* p_Xhi = (__half*)symp(g_Xhi);
    __half* p_Xlo = (__half*)symp(g_Xlo);
    __half* p_Whi = (__half*)symp(g_Whi);
    __half* p_Wlo = (__half*)symp(g_Wlo);
    float* p_xmean = (float*)symp(g_xmean);
    float* p_xA    = (float*)symp(g_xA);
    float* p_tM    = (float*)symp(g_tM);
    float* p_tA    = (float*)symp(g_tA);
    float* p_gn1   = (float*)symp(g_gn1);
    float* p_gn2   = (float*)symp(g_gn2);
    float* p_v     = (float*)symp(g_v);
    float* p_u     = (float*)symp(g_u);
    float* p_xg    = (float*)symp(g_xg);
    float* p_y     = (float*)symp(g_y);

    // 0) split x0 and W into fp16 hi/lo
    split_kernel<<<(NB * NL * NC / 4) / 256, 256>>>(x0, p_Xhi, p_Xlo);
    split_kernel<<<(NC * NC / 4) / 256, 256>>>(W, p_Whi, p_Wlo);

    // 1) tensor-core GEMM1 (fp16x3) with fused max/sum-over-L epilogue
    cudaFuncSetAttribute(gemm1_mma, cudaFuncAttributeMaxDynamicSharedMemorySize,
                         SM1_BYTES);
    dim3 g1(8, 512);
    gemm1_mma<<<g1, 256, SM1_BYTES>>>(p_Xhi, p_Xlo, p_Whi, p_Wlo);
    reduce_maxsum<<<(NB * NC) / 256, 256>>>(b);

    // 2) pooled branches + GroupNorm
    dim3 gst(NC / 8, NB);
    small_gemm_T<<<gst, 256>>>(p_xmean, Wm, bm, p_tM);
    small_gemm_T<<<gst, 256>>>(p_xA, Wa, ba, p_tA);
    gn_kernel<<<NB, 1024>>>(p_tM, g1w, g1b, p_gn1);
    gn_kernel<<<NB, 1024>>>(p_tA, g2w, g2b, p_gn2);

    // 3) u = W^T(W1^T(gn1+gn2))
    dim3 gsn(NC / 256, NB);
    small_gemm_N<false><<<gsn, 256>>>(p_gn1, W1, p_v);
    small_gemm_N<true ><<<gsn, 256>>>(p_gn2, W1, p_v);
    small_gemm_N<false><<<gsn, 256>>>(p_v, W, p_u);

    // 4) scores, 5) top-k + gather, 6) exact fp32 recompute of selected rows
    dim3 gdot(NL / 8, NB);
    dot_kernel<<<gdot, 256>>>(x0);
    topk_kernel<<<NB, 256>>>();
    gather_kernel<<<NB * KSEL, 256>>>(x0);
    dim3 gg2((NB * KSEL) / 64, NC / 64);
    gemm2<<<gg2, 256>>>(p_xg, W, b, p_y);
    gemm2<<<gg2, 256>>>(p_y, W1, b1, out);
}

// round 5
// speedup vs baseline: 3.3185x; 1.8446x over previous
#include <cuda_runtime.h>
#include <cuda_fp16.h>
#include <float.h>
#include <stdint.h>
#include <math.h>

#define NB 32
#define NL 2048
#define NC 1024
#define KSEL 20
#define GNEPS 1e-5f
#define NLT 16

// ---------------- scratch (device globals; no allocations allowed) ----------
__device__ __half g_Xhi[(size_t)NB * NL * NC];
__device__ __half g_Whi[NC * NC];
__device__ float4 g_cand[NLT * NB * NC];         // per-tile top2 (v1,l1,v2,l2)
__device__ int4  g_c3[NB * NC];                  // global top-3 candidate rows
__device__ float g_cpart[NB * 128 * NC];         // column-sum partials (16 rows each)
__device__ float g_colmean[NB * NC];
__device__ float g_xA[NB * NC];
__device__ float g_xmean[NB * NC];
__device__ float g_tM[NB * NC];
__device__ float g_tA[NB * NC];
__device__ float g_gn1[NB * NC];
__device__ float g_gn2[NB * NC];
__device__ float g_v[NB * NC];
__device__ float g_u[NB * NC];
__device__ float g_s[NB * NL];
__device__ int   g_top[NB * KSEL];
__device__ float g_xg[NB * KSEL * NC];
__device__ float g_y[NB * KSEL * NC];

// ----------------------------- helpers --------------------------------------
__device__ __forceinline__ uint32_t smem_u32(const void* p) {
    uint32_t a;
    asm("{ .reg .u64 t; cvta.to.shared.u64 t, %1; cvt.u32.u64 %0, t; }"
        : "=r"(a) : "l"(p));
    return a;
}
#define CP_ASYNC16(dst, src) \
    asm volatile("cp.async.cg.shared.global [%0], [%1], 16;" :: "r"(dst), "l"(src) : "memory")
#define CP_COMMIT() asm volatile("cp.async.commit_group;" ::: "memory")
#define CP_WAIT2()  asm volatile("cp.async.wait_group 2;" ::: "memory")
#define MMA16816(c, a0, a1, a2, a3, b0, b1)                                \
    asm volatile("mma.sync.aligned.m16n8k16.row.col.f32.f16.f16.f32 "      \
        "{%0,%1,%2,%3}, {%4,%5,%6,%7}, {%8,%9}, {%0,%1,%2,%3};"            \
        : "+f"((c)[0]), "+f"((c)[1]), "+f"((c)[2]), "+f"((c)[3])           \
        : "r"(a0), "r"(a1), "r"(a2), "r"(a3), "r"(b0), "r"(b1))

// ---- split x0 -> fp16 hi, fused per-16-row column-sum partials -------------
// grid: NB*128 blocks (16 rows each), 256 threads (one float4 col-chunk each)
__global__ void __launch_bounds__(256)
split_colsum(const float* __restrict__ X0, __half* __restrict__ Xhi)
{
    int blk = blockIdx.x;                 // b*128 + chunk
    int b = blk >> 7, ch = blk & 127;
    int t = threadIdx.x;                  // col4 index 0..255
    size_t rowbase = ((size_t)b * NL + ch * 16) * NC;
    float4 s = make_float4(0.f, 0.f, 0.f, 0.f);
#pragma unroll
    for (int r = 0; r < 16; r++) {
        float4 v = *(const float4*)(X0 + rowbase + (size_t)r * NC + t * 4);
        s.x += v.x; s.y += v.y; s.z += v.z; s.w += v.w;
        __half2* hp = (__half2*)(Xhi + rowbase + (size_t)r * NC + t * 4);
        hp[0] = __floats2half2_rn(v.x, v.y);
        hp[1] = __floats2half2_rn(v.z, v.w);
    }
    *(float4*)(g_cpart + (size_t)blk * NC + t * 4) = s;
}

__global__ void wsplit(const float* __restrict__ W)
{
    size_t i = (size_t)blockIdx.x * 256 + threadIdx.x;
    float4 v = ((const float4*)W)[i];
    __half2* hp = (__half2*)(g_Whi + i * 4);
    hp[0] = __floats2half2_rn(v.x, v.y);
    hp[1] = __floats2half2_rn(v.z, v.w);
}

__global__ void colmean_reduce()
{
    int idx = blockIdx.x * 256 + threadIdx.x;   // b*NC + c
    int b = idx >> 10, c = idx & 1023;
    float s = 0.f;
#pragma unroll 8
    for (int p = 0; p < 128; p++)
        s += g_cpart[((size_t)(b * 128 + p)) * NC + c];
    g_colmean[idx] = s * (1.0f / NL);
}

// ---------------------------------------------------------------------------
// GEMM1 approx: x[m,d] = x0_hi[m,:] . W_hi[d,:], single fp16 product.
// 128x128 CTA tile, 8 warps 64x32, 4-stage cp.async, k-chunk 16.
// Epilogue: per-column top-2 (value, row) over the tile's 128 rows.
// ---------------------------------------------------------------------------
#define ST_BYTES 8192

__global__ void __launch_bounds__(256, 2)
gemm1_mma(const __half* __restrict__ Xhi, const __half* __restrict__ Whi)
{
    __shared__ char smem[4 * ST_BYTES];
    const int tid = threadIdx.x;
    const int ntile = blockIdx.x, mtile = blockIdx.y;
    const int wid = tid >> 5, lane = tid & 31;
    const int wm = wid >> 2, wn = wid & 3;
    const int gr = lane >> 2, q = lane & 3;
    const uint32_t sbase = smem_u32(smem);

    const int arow = tid >> 1, aseg = tid & 1;
    const size_t gA = (size_t)(mtile * 128 + arow) * NC + aseg * 8;
    const size_t gB = (size_t)(ntile * 128 + arow) * NC + aseg * 8;
    const uint32_t dsto = arow * 32 + ((aseg * 16) ^ (((arow >> 2) & 1) * 16));

    float acc[4][4][4];
#pragma unroll
    for (int i = 0; i < 4; i++)
#pragma unroll
        for (int j = 0; j < 4; j++)
#pragma unroll
            for (int r = 0; r < 4; r++) acc[i][j][r] = 0.f;

    uint32_t aoff0[4], aoff2[4], boff0[4], boff1[4];
#pragma unroll
    for (int mt = 0; mt < 4; mt++) {
        int r = wm * 64 + mt * 16 + gr;
        int f = ((r >> 2) & 1) * 16;
        aoff0[mt] = r * 32 + ((q * 4) ^ f);
        aoff2[mt] = r * 32 + ((16 + q * 4) ^ f);
    }
#pragma unroll
    for (int nt = 0; nt < 4; nt++) {
        int n = wn * 32 + nt * 8 + gr;
        int f = ((n >> 2) & 1) * 16;
        boff0[nt] = n * 32 + ((q * 4) ^ f);
        boff1[nt] = n * 32 + ((16 + q * 4) ^ f);
    }

    auto issue = [&](int s, int k0) {
        uint32_t d = sbase + s * ST_BYTES + dsto;
        CP_ASYNC16(d,         Xhi + gA + k0);
        CP_ASYNC16(d + 4096u, Whi + gB + k0);
    };

    issue(0, 0);  CP_COMMIT();
    issue(1, 16); CP_COMMIT();
    issue(2, 32); CP_COMMIT();

    for (int ks = 0; ks < 64; ks++) {
        CP_WAIT2();
        __syncthreads();
        if (ks < 61) issue((ks + 3) & 3, (ks + 3) * 16);
        CP_COMMIT();

        const char* st = smem + (ks & 3) * ST_BYTES;
        uint32_t Bh[4][2];
#pragma unroll
        for (int nt = 0; nt < 4; nt++) {
            Bh[nt][0] = *(const uint32_t*)(st + 4096 + boff0[nt]);
            Bh[nt][1] = *(const uint32_t*)(st + 4096 + boff1[nt]);
        }
#pragma unroll
        for (int mt = 0; mt < 4; mt++) {
            uint32_t A0 = *(const uint32_t*)(st + aoff0[mt]);
            uint32_t A1 = *(const uint32_t*)(st + aoff0[mt] + 256);
            uint32_t A2 = *(const uint32_t*)(st + aoff2[mt]);
            uint32_t A3 = *(const uint32_t*)(st + aoff2[mt] + 256);
#pragma unroll
            for (int nt = 0; nt < 4; nt++)
                MMA16816(acc[mt][nt], A0, A1, A2, A3, Bh[nt][0], Bh[nt][1]);
        }
    }

    // ---- epilogue: per-column top-2 (value,row) over 128 rows ----
    __syncthreads();
    float4* sc = (float4*)smem;              // [2][128]
    const int lt = mtile & 15, b = mtile >> 4;
    const int lbase = lt * 128;

#pragma unroll
    for (int nt = 0; nt < 4; nt++) {
#pragma unroll
        for (int c = 0; c < 2; c++) {
            float bv1 = -FLT_MAX, bv2 = -FLT_MAX;
            int bl1 = 0, bl2 = 0;
#define INS(V, L) do { float _v = (V); int _l = (L);                       \
    if (_v > bv1) { bv2 = bv1; bl2 = bl1; bv1 = _v; bl1 = _l; }            \
    else if (_v > bv2) { bv2 = _v; bl2 = _l; } } while (0)
#pragma unroll
            for (int mt = 0; mt < 4; mt++) {
#pragma unroll
                for (int h = 0; h < 2; h++) {
                    int l = lbase + wm * 64 + mt * 16 + gr + 8 * h;
                    INS(acc[mt][nt][c + 2 * h], l);
                }
            }
#pragma unroll
            for (int o = 4; o <= 16; o <<= 1) {
                float ov1 = __shfl_xor_sync(0xffffffffu, bv1, o);
                float ov2 = __shfl_xor_sync(0xffffffffu, bv2, o);
                int ol1 = __shfl_xor_sync(0xffffffffu, bl1, o);
                int ol2 = __shfl_xor_sync(0xffffffffu, bl2, o);
                INS(ov1, ol1);
                INS(ov2, ol2);
            }
            if (gr == 0) {
                int col = wn * 32 + nt * 8 + q * 2 + c;
                sc[wm * 128 + col] = make_float4(bv1, __int_as_float(bl1),
                                                 bv2, __int_as_float(bl2));
            }
#undef INS
        }
    }
    __syncthreads();
    if (tid < 128) {
        float4 a = sc[tid], o = sc[128 + tid];
        float bv1 = a.x, bv2 = a.z;
        int bl1 = __float_as_int(a.y), bl2 = __float_as_int(a.w);
        float cv[2] = { o.x, o.z };
        int cl[2] = { __float_as_int(o.y), __float_as_int(o.w) };
#pragma unroll
        for (int j = 0; j < 2; j++) {
            if (cv[j] > bv1) { bv2 = bv1; bl2 = bl1; bv1 = cv[j]; bl1 = cl[j]; }
            else if (cv[j] > bv2) { bv2 = cv[j]; bl2 = cl[j]; }
        }
        g_cand[((size_t)lt * NB + b) * NC + ntile * 128 + tid] =
            make_float4(bv1, __int_as_float(bl1), bv2, __int_as_float(bl2));
    }
}

// global top-3 candidate rows per (b,d) from 16 tiles x top2
__global__ void reduce_cand()
{
    int idx = blockIdx.x * 256 + threadIdx.x;   // b*NC + c
    int b = idx >> 10, c = idx & 1023;
    float v0 = -FLT_MAX, v1 = -FLT_MAX, v2 = -FLT_MAX;
    int l0 = 0, l1 = 0, l2 = 0;
#pragma unroll
    for (int t = 0; t < NLT; t++) {
        float4 q = g_cand[((size_t)t * NB + b) * NC + c];
#pragma unroll
        for (int j = 0; j < 2; j++) {
            float v = j ? q.z : q.x;
            int l = __float_as_int(j ? q.w : q.y);
            if (v > v0) { v2 = v1; l2 = l1; v1 = v0; l1 = l0; v0 = v; l0 = l; }
            else if (v > v1) { v2 = v1; l2 = l1; v1 = v; l1 = l; }
            else if (v > v2) { v2 = v; l2 = l; }
        }
    }
    g_c3[idx] = make_int4(l0, l1, l2, 0);
}

// exact fp32 recompute of the 3 candidates -> x_A (bias folded)
__global__ void __launch_bounds__(256)
exact_max(const float* __restrict__ X0, const float* __restrict__ W,
          const float* __restrict__ bias)
{
    int b = blockIdx.y;
    int wid = threadIdx.x >> 5, lane = threadIdx.x & 31;
    int d = blockIdx.x * 8 + wid;
    int4 c3 = g_c3[b * NC + d];
    const float4* wr = (const float4*)(W + (size_t)d * NC);
    const float4* x1 = (const float4*)(X0 + ((size_t)b * NL + c3.x) * NC);
    const float4* x2 = (const float4*)(X0 + ((size_t)b * NL + c3.y) * NC);
    const float4* x3 = (const float4*)(X0 + ((size_t)b * NL + c3.z) * NC);
    float a1 = 0.f, a2 = 0.f, a3 = 0.f;
#pragma unroll 4
    for (int i = lane; i < NC / 4; i += 32) {
        float4 w4 = __ldg(&wr[i]);
        float4 p = __ldg(&x1[i]);
        a1 += w4.x * p.x + w4.y * p.y + w4.z * p.z + w4.w * p.w;
        p = __ldg(&x2[i]);
        a2 += w4.x * p.x + w4.y * p.y + w4.z * p.z + w4.w * p.w;
        p = __ldg(&x3[i]);
        a3 += w4.x * p.x + w4.y * p.y + w4.z * p.z + w4.w * p.w;
    }
#pragma unroll
    for (int o = 16; o; o >>= 1) {
        a1 += __shfl_xor_sync(0xffffffffu, a1, o);
        a2 += __shfl_xor_sync(0xffffffffu, a2, o);
        a3 += __shfl_xor_sync(0xffffffffu, a3, o);
    }
    if (lane == 0)
        g_xA[b * NC + d] = fmaxf(a1, fmaxf(a2, a3)) + __ldg(bias + d);
}

// out[b,n] = sum_k A[b,k]*M[n,k] + bias[n]
__global__ void __launch_bounds__(256)
small_gemm_T(const float* __restrict__ Ain, const float* __restrict__ M,
             const float* __restrict__ bias, float* __restrict__ out)
{
    int b = blockIdx.y;
    __shared__ float sA[NC];
    int tid = threadIdx.x;
    for (int i = tid; i < NC; i += 256) sA[i] = Ain[b * NC + i];
    __syncthreads();
    int warp = tid >> 5, lane = tid & 31;
    int n = blockIdx.x * 8 + warp;
    const float4* Mr = (const float4*)(M + (size_t)n * NC);
    const float4* Ar = (const float4*)sA;
    float acc = 0.f;
#pragma unroll 4
    for (int i = lane; i < NC / 4; i += 32) {
        float4 m4 = __ldg(&Mr[i]);
        float4 a4 = Ar[i];
        acc += m4.x * a4.x + m4.y * a4.y + m4.z * a4.z + m4.w * a4.w;
    }
#pragma unroll
    for (int o = 16; o; o >>= 1) acc += __shfl_xor_sync(0xffffffffu, acc, o);
    if (lane == 0) out[b * NC + n] = acc + __ldg(bias + n);
}

// GroupNorm: 32 groups of 32 channels (group == warp)
__global__ void gn_kernel(const float* __restrict__ t, const float* __restrict__ w,
                          const float* __restrict__ bb, float* __restrict__ o)
{
    int b = blockIdx.x;
    int c = threadIdx.x;
    float v = t[b * NC + c];
    float s = v;
#pragma unroll
    for (int off = 16; off; off >>= 1) s += __shfl_xor_sync(0xffffffffu, s, off);
    float mean = s * (1.f / 32.f);
    float d = v - mean;
    float qq = d * d;
#pragma unroll
    for (int off = 16; off; off >>= 1) qq += __shfl_xor_sync(0xffffffffu, qq, off);
    float var = qq * (1.f / 32.f);
    o[b * NC + c] = d * rsqrtf(var + GNEPS) * __ldg(w + c) + __ldg(bb + c);
}

// out[b,c] (+)= sum_d A[b,d]*M[d,c]
template <bool ACCUM>
__global__ void __launch_bounds__(256)
small_gemm_N(const float* __restrict__ Ain, const float* __restrict__ M,
             float* __restrict__ out)
{
    int b = blockIdx.y;
    int c = blockIdx.x * 256 + threadIdx.x;
    __shared__ float sA[NC];
    for (int i = threadIdx.x; i < NC; i += 256) sA[i] = Ain[b * NC + i];
    __syncthreads();
    float acc = ACCUM ? out[b * NC + c] : 0.f;
#pragma unroll 8
    for (int d = 0; d < NC; d++)
        acc += sA[d] * __ldg(M + (size_t)d * NC + c);
    out[b * NC + c] = acc;
}

// s[b,l] = x0[b,l,:] . u[b,:]
__global__ void __launch_bounds__(256)
dot_kernel(const float* __restrict__ X0)
{
    int b = blockIdx.y;
    __shared__ float su[NC];
    for (int i = threadIdx.x; i < NC; i += 256) su[i] = g_u[b * NC + i];
    __syncthreads();
    int warp = threadIdx.x >> 5, lane = threadIdx.x & 31;
    int l = blockIdx.x * 8 + warp;
    const float4* xr = (const float4*)(X0 + ((size_t)b * NL + l) * NC);
    const float4* ur = (const float4*)su;
    float acc = 0.f;
#pragma unroll 4
    for (int i = lane; i < NC / 4; i += 32) {
        float4 x = __ldg(&xr[i]);
        float4 u = ur[i];
        acc += x.x * u.x + x.y * u.y + x.z * u.z + x.w * u.w;
    }
#pragma unroll
    for (int o = 16; o; o >>= 1) acc += __shfl_xor_sync(0xffffffffu, acc, o);
    if (lane == 0) g_s[b * NL + l] = acc;
}

// Iterative top-20 per batch (ties -> lowest index)
__global__ void __launch_bounds__(256) topk_kernel()
{
    int b = blockIdx.x;
    __shared__ float vals[NL];
    __shared__ float rmx[256];
    __shared__ int   rix[256];
    int tid = threadIdx.x;
    for (int i = tid; i < NL; i += 256) vals[i] = g_s[b * NL + i];
    __syncthreads();
    for (int it = 0; it < KSEL; it++) {
        float m = -FLT_MAX; int mi = 0;
        for (int i = tid; i < NL; i += 256) {
            float v = vals[i];
            if (v > m) { m = v; mi = i; }
        }
        rmx[tid] = m; rix[tid] = mi;
        __syncthreads();
        for (int st = 128; st > 0; st >>= 1) {
            if (tid < st) {
                float vo = rmx[tid + st]; int io = rix[tid + st];
                if (vo > rmx[tid] || (vo == rmx[tid] && io < rix[tid])) {
                    rmx[tid] = vo; rix[tid] = io;
                }
            }
            __syncthreads();
        }
        if (tid == 0) {
            g_top[b * KSEL + it] = rix[0];
            vals[rix[0]] = -FLT_MAX;
        }
        __syncthreads();
    }
}

__global__ void gather_kernel(const float* __restrict__ X0)
{
    int r = blockIdx.x;
    int b = r / KSEL;
    int l = g_top[r];
    const float4* src = (const float4*)(X0 + ((size_t)b * NL + l) * NC);
    float4* dst = (float4*)(g_xg + (size_t)r * NC);
    dst[threadIdx.x] = src[threadIdx.x];
}

// out[m,n] = sum_k A[m,k]*Bw[n,k] + bias[n]; exact fp32 for selected rows
__global__ void __launch_bounds__(256)
gemm2(const float* __restrict__ A, const float* __restrict__ Bw,
      const float* __restrict__ bias, float* __restrict__ out)
{
    const int mtile = blockIdx.x, ntile = blockIdx.y;
    __shared__ float As[16][64];
    __shared__ float Bs[16][64];
    int tid = threadIdx.x;
    int tx = tid & 15, ty = tid >> 4;
    const float* Ap = A + (size_t)mtile * 64 * NC;
    const float* Bp = Bw + (size_t)ntile * 64 * NC;
    int lrow = tid >> 2;
    int lk4  = (tid & 3) * 4;

    float acc[4][4];
#pragma unroll
    for (int i = 0; i < 4; i++)
#pragma unroll
        for (int j = 0; j < 4; j++) acc[i][j] = 0.f;

    float4 a4 = *(const float4*)(Ap + (size_t)lrow * NC + lk4);
    float4 b4 = *(const float4*)(Bp + (size_t)lrow * NC + lk4);

    for (int k0 = 0; k0 < NC; k0 += 16) {
        __syncthreads();
        As[lk4 + 0][lrow] = a4.x; As[lk4 + 1][lrow] = a4.y;
        As[lk4 + 2][lrow] = a4.z; As[lk4 + 3][lrow] = a4.w;
        Bs[lk4 + 0][lrow] = b4.x; Bs[lk4 + 1][lrow] = b4.y;
        Bs[lk4 + 2][lrow] = b4.z; Bs[lk4 + 3][lrow] = b4.w;
        __syncthreads();
        if (k0 + 16 < NC) {
            a4 = *(const float4*)(Ap + (size_t)lrow * NC + k0 + 16 + lk4);
            b4 = *(const float4*)(Bp + (size_t)lrow * NC + k0 + 16 + lk4);
        }
#pragma unroll
        for (int kk = 0; kk < 16; kk++) {
            float ra[4], rb[4];
            *(float4*)ra = *(const float4*)(&As[kk][ty * 4]);
            *(float4*)rb = *(const float4*)(&Bs[kk][tx * 4]);
#pragma unroll
            for (int i = 0; i < 4; i++)
#pragma unroll
                for (int j = 0; j < 4; j++)
                    acc[i][j] += ra[i] * rb[j];
        }
    }
#pragma unroll
    for (int j = 0; j < 4; j++) {
        float bd = __ldg(bias + ntile * 64 + tx * 4 + j);
#pragma unroll
        for (int i = 0; i < 4; i++)
            out[((size_t)mtile * 64 + ty * 4 + i) * NC + ntile * 64 + tx * 4 + j] =
                acc[i][j] + bd;
    }
}

// ---------------------------------------------------------------------------
static void* symp(const void* symbol)
{
    void* p = nullptr;
    cudaGetSymbolAddress(&p, symbol);
    return p;
}

extern "C" void kernel_launch(void* const* d_in, const int* in_sizes, int n_in,
                              void* d_out, int out_size)
{
    const float* x0  = (const float*)d_in[0];
    const float* W   = (const float*)d_in[1];
    const float* b   = (const float*)d_in[2];
    const float* W1  = (const float*)d_in[3];
    const float* b1  = (const float*)d_in[4];
    const float* Wm  = (const float*)d_in[5];
    const float* bm  = (const float*)d_in[6];
    const float* Wa  = (const float*)d_in[7];
    const float* ba  = (const float*)d_in[8];
    const float* g1w = (const float*)d_in[9];
    const float* g1b = (const float*)d_in[10];
    const float* g2w = (const float*)d_in[11];
    const float* g2b = (const float*)d_in[12];
    float* out = (float*)d_out;

    __half* p_Xhi = (__half*)symp(g_Xhi);
    __half* p_Whi = (__half*)symp(g_Whi);
    float* p_colmean = (float*)symp(g_colmean);
    float* p_xmean = (float*)symp(g_xmean);
    float* p_xA    = (float*)symp(g_xA);
    float* p_tM    = (float*)symp(g_tM);
    float* p_tA    = (float*)symp(g_tA);
    float* p_gn1   = (float*)symp(g_gn1);
    float* p_gn2   = (float*)symp(g_gn2);
    float* p_v     = (float*)symp(g_v);
    float* p_u     = (float*)symp(g_u);
    float* p_xg    = (float*)symp(g_xg);
    float* p_y     = (float*)symp(g_y);

    // 0) split x0 -> fp16 hi (+ fused column-sum partials); split W
    split_colsum<<<NB * 128, 256>>>(x0, p_Xhi);
    wsplit<<<(NC * NC / 4) / 256, 256>>>(W);
    colmean_reduce<<<(NB * NC) / 256, 256>>>();

    // 1) approx GEMM1 (single fp16 product) with top-2-per-tile epilogue
    dim3 g1(8, 512);
    gemm1_mma<<<g1, 256>>>(p_Xhi, p_Whi);
    reduce_cand<<<(NB * NC) / 256, 256>>>();
    dim3 gex(NC / 8, NB);
    exact_max<<<gex, 256>>>(x0, W, b);

    // 2) exact mean path + pooled branches + GroupNorm
    dim3 gst(NC / 8, NB);
    small_gemm_T<<<gst, 256>>>(p_colmean, W, b, p_xmean);
    small_gemm_T<<<gst, 256>>>(p_xmean, Wm, bm, p_tM);
    small_gemm_T<<<gst, 256>>>(p_xA, Wa, ba, p_tA);
    gn_kernel<<<NB, 1024>>>(p_tM, g1w, g1b, p_gn1);
    gn_kernel<<<NB, 1024>>>(p_tA, g2w, g2b, p_gn2);

    // 3) u = W^T(W1^T(gn1+gn2))
    dim3 gsn(NC / 256, NB);
    small_gemm_N<false><<<gsn, 256>>>(p_gn1, W1, p_v);
    small_gemm_N<true ><<<gsn, 256>>>(p_gn2, W1, p_v);
    small_gemm_N<false><<<gsn, 256>>>(p_v, W, p_u);

    // 4) scores, 5) top-k + gather, 6) exact fp32 recompute of selected rows
    dim3 gdot(NL / 8, NB);
    dot_kernel<<<gdot, 256>>>(x0);
    topk_kernel<<<NB, 256>>>();
    gather_kernel<<<NB * KSEL, 256>>>(x0);
    dim3 gg2((NB * KSEL) / 64, NC / 64);
    gemm2<<<gg2, 256>>>(p_xg, W, b, p_y);
    gemm2<<<gg2, 256>>>(p_y, W1, b1, out);
}

// round 6
// speedup vs baseline: 3.9321x; 1.1849x over previous
#include <cuda_runtime.h>
#include <cuda_fp16.h>
#include <float.h>
#include <stdint.h>
#include <math.h>

#define NB 32
#define NL 2048
#define NC 1024
#define KSEL 20
#define GNEPS 1e-5f
#define NLT 16

// ---------------- scratch (device globals; no allocations allowed) ----------
__device__ __half g_Xhi[(size_t)NB * NL * NC];
__device__ __half g_Whi[NC * NC];
__device__ __half g_Wlo[NC * NC];
__device__ __half g_W1hi[NC * NC];
__device__ __half g_W1lo[NC * NC];
__device__ float4 g_cand[NLT * NB * NC];
__device__ int4  g_c3[NB * NC];
__device__ float g_cpart[NB * 128 * NC];
__device__ float g_colmean[NB * NC];
__device__ float g_xA[NB * NC];
__device__ float g_xmean[NB * NC];
__device__ float g_tM[NB * NC];
__device__ float g_tA[NB * NC];
__device__ float g_gn1[NB * NC];
__device__ float g_gn2[NB * NC];
__device__ float g_v[NB * NC];
__device__ float g_u[NB * NC];
__device__ float g_s[NB * NL];
__device__ int   g_top[NB * KSEL];
__device__ __half g_xghi[NB * KSEL * NC];
__device__ __half g_xglo[NB * KSEL * NC];
__device__ __half g_yhi[NB * KSEL * NC];
__device__ __half g_ylo[NB * KSEL * NC];

// ----------------------------- helpers --------------------------------------
__device__ __forceinline__ uint32_t smem_u32(const void* p) {
    uint32_t a;
    asm("{ .reg .u64 t; cvta.to.shared.u64 t, %1; cvt.u32.u64 %0, t; }"
        : "=r"(a) : "l"(p));
    return a;
}
#define CP_ASYNC16(dst, src) \
    asm volatile("cp.async.cg.shared.global [%0], [%1], 16;" :: "r"(dst), "l"(src) : "memory")
#define CP_COMMIT() asm volatile("cp.async.commit_group;" ::: "memory")
#define CP_WAIT2()  asm volatile("cp.async.wait_group 2;" ::: "memory")
#define CP_WAIT1()  asm volatile("cp.async.wait_group 1;" ::: "memory")
#define MMA16816(c, a0, a1, a2, a3, b0, b1)                                \
    asm volatile("mma.sync.aligned.m16n8k16.row.col.f32.f16.f16.f32 "      \
        "{%0,%1,%2,%3}, {%4,%5,%6,%7}, {%8,%9}, {%0,%1,%2,%3};"            \
        : "+f"((c)[0]), "+f"((c)[1]), "+f"((c)[2]), "+f"((c)[3])           \
        : "r"(a0), "r"(a1), "r"(a2), "r"(a3), "r"(b0), "r"(b1))
#define LDSM4(r0, r1, r2, r3, addr)                                        \
    asm volatile("ldmatrix.sync.aligned.m8n8.x4.shared.b16 {%0,%1,%2,%3}, [%4];" \
        : "=r"(r0), "=r"(r1), "=r"(r2), "=r"(r3) : "r"(addr))

// ---- split x0 -> fp16 hi, fused per-16-row column-sum partials -------------
__global__ void __launch_bounds__(256)
split_colsum(const float* __restrict__ X0, __half* __restrict__ Xhi)
{
    int blk = blockIdx.x;
    int b = blk >> 7, ch = blk & 127;
    int t = threadIdx.x;
    size_t rowbase = ((size_t)b * NL + ch * 16) * NC;
    float4 s = make_float4(0.f, 0.f, 0.f, 0.f);
#pragma unroll
    for (int r = 0; r < 16; r++) {
        float4 v = *(const float4*)(X0 + rowbase + (size_t)r * NC + t * 4);
        s.x += v.x; s.y += v.y; s.z += v.z; s.w += v.w;
        __half2* hp = (__half2*)(Xhi + rowbase + (size_t)r * NC + t * 4);
        hp[0] = __floats2half2_rn(v.x, v.y);
        hp[1] = __floats2half2_rn(v.z, v.w);
    }
    *(float4*)(g_cpart + (size_t)blk * NC + t * 4) = s;
}

// split W (or W1) into fp16 hi/lo
__global__ void wsplit(const float* __restrict__ W, __half* __restrict__ hi,
                       __half* __restrict__ lo)
{
    size_t i = (size_t)blockIdx.x * 256 + threadIdx.x;
    float4 v = ((const float4*)W)[i];
    __half h0 = __float2half_rn(v.x), h1 = __float2half_rn(v.y);
    __half h2 = __float2half_rn(v.z), h3 = __float2half_rn(v.w);
    ((__half2*)hi)[i * 2 + 0] = __halves2half2(h0, h1);
    ((__half2*)hi)[i * 2 + 1] = __halves2half2(h2, h3);
    ((__half2*)lo)[i * 2 + 0] = __floats2half2_rn(v.x - __half2float(h0),
                                                  v.y - __half2float(h1));
    ((__half2*)lo)[i * 2 + 1] = __floats2half2_rn(v.z - __half2float(h2),
                                                  v.w - __half2float(h3));
}

__global__ void colmean_reduce()
{
    int idx = blockIdx.x * 256 + threadIdx.x;
    int b = idx >> 10, c = idx & 1023;
    float s = 0.f;
#pragma unroll 8
    for (int p = 0; p < 128; p++)
        s += g_cpart[((size_t)(b * 128 + p)) * NC + c];
    g_colmean[idx] = s * (1.0f / NL);
}

// ---------------------------------------------------------------------------
// GEMM1 approx: single fp16 product, ldmatrix fragment loads.
// 128x128 CTA tile, 8 warps 64x32, 4-stage cp.async, k-chunk 16.
// Epilogue: per-column top-2 (value,row) over the tile's 128 rows.
// ---------------------------------------------------------------------------
#define ST_BYTES 8192

__global__ void __launch_bounds__(256, 2)
gemm1_mma(const __half* __restrict__ Xhi, const __half* __restrict__ Whi)
{
    __shared__ char smem[4 * ST_BYTES];
    const int tid = threadIdx.x;
    const int ntile = blockIdx.x, mtile = blockIdx.y;
    const int wid = tid >> 5, lane = tid & 31;
    const int wm = wid >> 2, wn = wid & 3;
    const int gr = lane >> 2, q = lane & 3;
    const uint32_t sbase = smem_u32(smem);

    const int arow = tid >> 1, aseg = tid & 1;
    const size_t gA = (size_t)(mtile * 128 + arow) * NC + aseg * 8;
    const size_t gB = (size_t)(ntile * 128 + arow) * NC + aseg * 8;
    const uint32_t dsto = arow * 32 + ((aseg * 16) ^ (((arow >> 2) & 1) * 16));

    float acc[4][4][4];
#pragma unroll
    for (int i = 0; i < 4; i++)
#pragma unroll
        for (int j = 0; j < 4; j++)
#pragma unroll
            for (int r = 0; r < 4; r++) acc[i][j][r] = 0.f;

    // ldmatrix addresses (relative to stage base)
    const int arl = (lane & 7) + ((lane >> 3) & 1) * 8;   // row within 16
    const int ac = lane >> 4;                              // k8 chunk
    uint32_t aoffs[4];
#pragma unroll
    for (int mt = 0; mt < 4; mt++) {
        int r = wm * 64 + mt * 16 + arl;
        aoffs[mt] = r * 32 + ((ac * 16) ^ (((r >> 2) & 1) * 16));
    }
    uint32_t boffs[2];
#pragma unroll
    for (int p = 0; p < 2; p++) {
        int g = lane >> 3;
        int n = wn * 32 + p * 16 + (g >> 1) * 8 + (lane & 7);
        int c = g & 1;
        boffs[p] = 4096 + n * 32 + ((c * 16) ^ (((n >> 2) & 1) * 16));
    }

    auto issue = [&](int s, int k0) {
        uint32_t d = sbase + s * ST_BYTES + dsto;
        CP_ASYNC16(d,         Xhi + gA + k0);
        CP_ASYNC16(d + 4096u, Whi + gB + k0);
    };

    issue(0, 0);  CP_COMMIT();
    issue(1, 16); CP_COMMIT();
    issue(2, 32); CP_COMMIT();

    for (int ks = 0; ks < 64; ks++) {
        CP_WAIT2();
        __syncthreads();
        if (ks < 61) issue((ks + 3) & 3, (ks + 3) * 16);
        CP_COMMIT();

        const uint32_t st = sbase + (ks & 3) * ST_BYTES;
        uint32_t bf[8];
        LDSM4(bf[0], bf[1], bf[2], bf[3], st + boffs[0]);
        LDSM4(bf[4], bf[5], bf[6], bf[7], st + boffs[1]);
#pragma unroll
        for (int mt = 0; mt < 4; mt++) {
            uint32_t A0, A1, A2, A3;
            LDSM4(A0, A1, A2, A3, st + aoffs[mt]);
#pragma unroll
            for (int nt = 0; nt < 4; nt++)
                MMA16816(acc[mt][nt], A0, A1, A2, A3, bf[nt * 2], bf[nt * 2 + 1]);
        }
    }

    // ---- epilogue: per-column top-2 (value,row) over 128 rows ----
    __syncthreads();
    float4* sc = (float4*)smem;
    const int lt = mtile & 15, b = mtile >> 4;
    const int lbase = lt * 128;

#pragma unroll
    for (int nt = 0; nt < 4; nt++) {
#pragma unroll
        for (int c = 0; c < 2; c++) {
            float bv1 = -FLT_MAX, bv2 = -FLT_MAX;
            int bl1 = 0, bl2 = 0;
#define INS(V, L) do { float _v = (V); int _l = (L);                       \
    if (_v > bv1) { bv2 = bv1; bl2 = bl1; bv1 = _v; bl1 = _l; }            \
    else if (_v > bv2) { bv2 = _v; bl2 = _l; } } while (0)
#pragma unroll
            for (int mt = 0; mt < 4; mt++) {
#pragma unroll
                for (int h = 0; h < 2; h++) {
                    int l = lbase + wm * 64 + mt * 16 + gr + 8 * h;
                    INS(acc[mt][nt][c + 2 * h], l);
                }
            }
#pragma unroll
            for (int o = 4; o <= 16; o <<= 1) {
                float ov1 = __shfl_xor_sync(0xffffffffu, bv1, o);
                float ov2 = __shfl_xor_sync(0xffffffffu, bv2, o);
                int ol1 = __shfl_xor_sync(0xffffffffu, bl1, o);
                int ol2 = __shfl_xor_sync(0xffffffffu, bl2, o);
                INS(ov1, ol1);
                INS(ov2, ol2);
            }
            if (gr == 0) {
                int col = wn * 32 + nt * 8 + q * 2 + c;
                sc[wm * 128 + col] = make_float4(bv1, __int_as_float(bl1),
                                                 bv2, __int_as_float(bl2));
            }
#undef INS
        }
    }
    __syncthreads();
    if (tid < 128) {
        float4 a = sc[tid], o = sc[128 + tid];
        float bv1 = a.x, bv2 = a.z;
        int bl1 = __float_as_int(a.y), bl2 = __float_as_int(a.w);
        float cv[2] = { o.x, o.z };
        int cl[2] = { __float_as_int(o.y), __float_as_int(o.w) };
#pragma unroll
        for (int j = 0; j < 2; j++) {
            if (cv[j] > bv1) { bv2 = bv1; bl2 = bl1; bv1 = cv[j]; bl1 = cl[j]; }
            else if (cv[j] > bv2) { bv2 = cv[j]; bl2 = cl[j]; }
        }
        g_cand[((size_t)lt * NB + b) * NC + ntile * 128 + tid] =
            make_float4(bv1, __int_as_float(bl1), bv2, __int_as_float(bl2));
    }
}

// global top-3 candidate rows per (b,d)
__global__ void reduce_cand()
{
    int idx = blockIdx.x * 256 + threadIdx.x;
    int b = idx >> 10, c = idx & 1023;
    float v0 = -FLT_MAX, v1 = -FLT_MAX, v2 = -FLT_MAX;
    int l0 = 0, l1 = 0, l2 = 0;
#pragma unroll
    for (int t = 0; t < NLT; t++) {
        float4 q = g_cand[((size_t)t * NB + b) * NC + c];
#pragma unroll
        for (int j = 0; j < 2; j++) {
            float v = j ? q.z : q.x;
            int l = __float_as_int(j ? q.w : q.y);
            if (v > v0) { v2 = v1; l2 = l1; v1 = v0; l1 = l0; v0 = v; l0 = l; }
            else if (v > v1) { v2 = v1; l2 = l1; v1 = v; l1 = l; }
            else if (v > v2) { v2 = v; l2 = l; }
        }
    }
    g_c3[idx] = make_int4(l0, l1, l2, 0);
}

// exact fp32 recompute of 3 candidates -> x_A (bias folded)
__global__ void __launch_bounds__(256)
exact_max(const float* __restrict__ X0, const float* __restrict__ W,
          const float* __restrict__ bias)
{
    int b = blockIdx.y;
    int wid = threadIdx.x >> 5, lane = threadIdx.x & 31;
    int d = blockIdx.x * 8 + wid;
    int4 c3 = g_c3[b * NC + d];
    const float4* wr = (const float4*)(W + (size_t)d * NC);
    const float4* x1 = (const float4*)(X0 + ((size_t)b * NL + c3.x) * NC);
    const float4* x2 = (const float4*)(X0 + ((size_t)b * NL + c3.y) * NC);
    const float4* x3 = (const float4*)(X0 + ((size_t)b * NL + c3.z) * NC);
    float a1 = 0.f, a2 = 0.f, a3 = 0.f;
#pragma unroll 4
    for (int i = lane; i < NC / 4; i += 32) {
        float4 w4 = __ldg(&wr[i]);
        float4 p = __ldg(&x1[i]);
        a1 += w4.x * p.x + w4.y * p.y + w4.z * p.z + w4.w * p.w;
        p = __ldg(&x2[i]);
        a2 += w4.x * p.x + w4.y * p.y + w4.z * p.z + w4.w * p.w;
        p = __ldg(&x3[i]);
        a3 += w4.x * p.x + w4.y * p.y + w4.z * p.z + w4.w * p.w;
    }
#pragma unroll
    for (int o = 16; o; o >>= 1) {
        a1 += __shfl_xor_sync(0xffffffffu, a1, o);
        a2 += __shfl_xor_sync(0xffffffffu, a2, o);
        a3 += __shfl_xor_sync(0xffffffffu, a3, o);
    }
    if (lane == 0)
        g_xA[b * NC + d] = fmaxf(a1, fmaxf(a2, a3)) + __ldg(bias + d);
}

// out[b,n] = sum_k A[b,k]*M[n,k] + bias[n]
__global__ void __launch_bounds__(256)
small_gemm_T(const float* __restrict__ Ain, const float* __restrict__ M,
             const float* __restrict__ bias, float* __restrict__ out)
{
    int b = blockIdx.y;
    __shared__ float sA[NC];
    int tid = threadIdx.x;
    for (int i = tid; i < NC; i += 256) sA[i] = Ain[b * NC + i];
    __syncthreads();
    int warp = tid >> 5, lane = tid & 31;
    int n = blockIdx.x * 8 + warp;
    const float4* Mr = (const float4*)(M + (size_t)n * NC);
    const float4* Ar = (const float4*)sA;
    float acc = 0.f;
#pragma unroll 4
    for (int i = lane; i < NC / 4; i += 32) {
        float4 m4 = __ldg(&Mr[i]);
        float4 a4 = Ar[i];
        acc += m4.x * a4.x + m4.y * a4.y + m4.z * a4.z + m4.w * a4.w;
    }
#pragma unroll
    for (int o = 16; o; o >>= 1) acc += __shfl_xor_sync(0xffffffffu, acc, o);
    if (lane == 0) out[b * NC + n] = acc + __ldg(bias + n);
}

// batched: z=0 -> (xmean,Wm,bm)->tM ; z=1 -> (xA,Wa,ba)->tA
__global__ void __launch_bounds__(256)
small_gemm_T2(const float* __restrict__ A0, const float* __restrict__ M0,
              const float* __restrict__ b0, float* __restrict__ o0,
              const float* __restrict__ A1, const float* __restrict__ M1,
              const float* __restrict__ b1, float* __restrict__ o1)
{
    const float* Ain = blockIdx.z ? A1 : A0;
    const float* M   = blockIdx.z ? M1 : M0;
    const float* bias= blockIdx.z ? b1 : b0;
    float* out       = blockIdx.z ? o1 : o0;
    int b = blockIdx.y;
    __shared__ float sA[NC];
    int tid = threadIdx.x;
    for (int i = tid; i < NC; i += 256) sA[i] = Ain[b * NC + i];
    __syncthreads();
    int warp = tid >> 5, lane = tid & 31;
    int n = blockIdx.x * 8 + warp;
    const float4* Mr = (const float4*)(M + (size_t)n * NC);
    const float4* Ar = (const float4*)sA;
    float acc = 0.f;
#pragma unroll 4
    for (int i = lane; i < NC / 4; i += 32) {
        float4 m4 = __ldg(&Mr[i]);
        float4 a4 = Ar[i];
        acc += m4.x * a4.x + m4.y * a4.y + m4.z * a4.z + m4.w * a4.w;
    }
#pragma unroll
    for (int o = 16; o; o >>= 1) acc += __shfl_xor_sync(0xffffffffu, acc, o);
    if (lane == 0) out[b * NC + n] = acc + __ldg(bias + n);
}

// both GroupNorms in one launch (y-dim selects branch)
__global__ void gn_kernel2(const float* __restrict__ t0, const float* __restrict__ w0,
                           const float* __restrict__ bb0, float* __restrict__ o0,
                           const float* __restrict__ t1, const float* __restrict__ w1,
                           const float* __restrict__ bb1, float* __restrict__ o1)
{
    const float* t = blockIdx.y ? t1 : t0;
    const float* w = blockIdx.y ? w1 : w0;
    const float* bb = blockIdx.y ? bb1 : bb0;
    float* o = blockIdx.y ? o1 : o0;
    int b = blockIdx.x;
    int c = threadIdx.x;
    float v = t[b * NC + c];
    float s = v;
#pragma unroll
    for (int off = 16; off; off >>= 1) s += __shfl_xor_sync(0xffffffffu, s, off);
    float mean = s * (1.f / 32.f);
    float d = v - mean;
    float qq = d * d;
#pragma unroll
    for (int off = 16; off; off >>= 1) qq += __shfl_xor_sync(0xffffffffu, qq, off);
    float var = qq * (1.f / 32.f);
    o[b * NC + c] = d * rsqrtf(var + GNEPS) * __ldg(w + c) + __ldg(bb + c);
}

// out[b,c] = sum_d (A0[b,d]+A1[b,d])*M[d,c]   (A1 may be null)
__global__ void __launch_bounds__(256)
small_gemm_N(const float* __restrict__ A0, const float* __restrict__ A1,
             const float* __restrict__ M, float* __restrict__ out)
{
    int b = blockIdx.y;
    int c = blockIdx.x * 256 + threadIdx.x;
    __shared__ float sA[NC];
    for (int i = threadIdx.x; i < NC; i += 256)
        sA[i] = A0[b * NC + i] + (A1 ? A1[b * NC + i] : 0.f);
    __syncthreads();
    float acc = 0.f;
#pragma unroll 8
    for (int d = 0; d < NC; d++)
        acc += sA[d] * __ldg(M + (size_t)d * NC + c);
    out[b * NC + c] = acc;
}

// s[b,l] = x0[b,l,:] . u[b,:]
__global__ void __launch_bounds__(256)
dot_kernel(const float* __restrict__ X0)
{
    int b = blockIdx.y;
    __shared__ float su[NC];
    for (int i = threadIdx.x; i < NC; i += 256) su[i] = g_u[b * NC + i];
    __syncthreads();
    int warp = threadIdx.x >> 5, lane = threadIdx.x & 31;
    int l = blockIdx.x * 8 + warp;
    const float4* xr = (const float4*)(X0 + ((size_t)b * NL + l) * NC);
    const float4* ur = (const float4*)su;
    float acc = 0.f;
#pragma unroll 4
    for (int i = lane; i < NC / 4; i += 32) {
        float4 x = __ldg(&xr[i]);
        float4 u = ur[i];
        acc += x.x * u.x + x.y * u.y + x.z * u.z + x.w * u.w;
    }
#pragma unroll
    for (int o = 16; o; o >>= 1) acc += __shfl_xor_sync(0xffffffffu, acc, o);
    if (lane == 0) g_s[b * NL + l] = acc;
}

// Iterative top-20 per batch (ties -> lowest index)
__global__ void __launch_bounds__(256) topk_kernel()
{
    int b = blockIdx.x;
    __shared__ float vals[NL];
    __shared__ float rmx[256];
    __shared__ int   rix[256];
    int tid = threadIdx.x;
    for (int i = tid; i < NL; i += 256) vals[i] = g_s[b * NL + i];
    __syncthreads();
    for (int it = 0; it < KSEL; it++) {
        float m = -FLT_MAX; int mi = 0;
        for (int i = tid; i < NL; i += 256) {
            float v = vals[i];
            if (v > m) { m = v; mi = i; }
        }
        rmx[tid] = m; rix[tid] = mi;
        __syncthreads();
        for (int st = 128; st > 0; st >>= 1) {
            if (tid < st) {
                float vo = rmx[tid + st]; int io = rix[tid + st];
                if (vo > rmx[tid] || (vo == rmx[tid] && io < rix[tid])) {
                    rmx[tid] = vo; rix[tid] = io;
                }
            }
            __syncthreads();
        }
        if (tid == 0) {
            g_top[b * KSEL + it] = rix[0];
            vals[rix[0]] = -FLT_MAX;
        }
        __syncthreads();
    }
}

// gather + split selected x0 rows to fp16 hi/lo
__global__ void gather_kernel(const float* __restrict__ X0)
{
    int r = blockIdx.x;
    int b = r / KSEL;
    int l = g_top[r];
    int t = threadIdx.x;                 // 256 threads x float4
    float4 v = *(const float4*)(X0 + ((size_t)b * NL + l) * NC + t * 4);
    __half h0 = __float2half_rn(v.x), h1 = __float2half_rn(v.y);
    __half h2 = __float2half_rn(v.z), h3 = __float2half_rn(v.w);
    __half2* hp = (__half2*)(g_xghi + (size_t)r * NC + t * 4);
    hp[0] = __halves2half2(h0, h1);
    hp[1] = __halves2half2(h2, h3);
    __half2* lp = (__half2*)(g_xglo + (size_t)r * NC + t * 4);
    lp[0] = __floats2half2_rn(v.x - __half2float(h0), v.y - __half2float(h1));
    lp[1] = __floats2half2_rn(v.z - __half2float(h2), v.w - __half2float(h3));
}

// ---------------------------------------------------------------------------
// fp16x3 GEMM for selected rows: out[m,n] = A[m,:].B[n,:] + bias[n].
// M=640 (5 mtiles of 128), N=K=1024. 3-stage cp.async + ldmatrix.
// SPLIT=1: write (acc+bias) as fp16 hi/lo; SPLIT=0: write fp32.
// ---------------------------------------------------------------------------
#define ST3_BYTES 16384

template <int SPLIT>
__global__ void __launch_bounds__(256, 1)
gemm_x3(const __half* __restrict__ Ahi, const __half* __restrict__ Alo,
        const __half* __restrict__ Bhi, const __half* __restrict__ Blo,
        const float* __restrict__ bias, float* __restrict__ outf,
        __half* __restrict__ ohi, __half* __restrict__ olo)
{
    __shared__ char smem[3 * ST3_BYTES];
    const int tid = threadIdx.x;
    const int ntile = blockIdx.x, mtile = blockIdx.y;
    const int wid = tid >> 5, lane = tid & 31;
    const int wm = wid >> 2, wn = wid & 3;
    const int gr = lane >> 2, q = lane & 3;
    const uint32_t sbase = smem_u32(smem);

    const int arow = tid >> 1, aseg = tid & 1;
    const size_t gA = (size_t)(mtile * 128 + arow) * NC + aseg * 8;
    const size_t gB = (size_t)(ntile * 128 + arow) * NC + aseg * 8;
    const uint32_t dsto = arow * 32 + ((aseg * 16) ^ (((arow >> 2) & 1) * 16));

    float acc[4][4][4];
#pragma unroll
    for (int i = 0; i < 4; i++)
#pragma unroll
        for (int j = 0; j < 4; j++)
#pragma unroll
            for (int r = 0; r < 4; r++) acc[i][j][r] = 0.f;

    const int arl = (lane & 7) + ((lane >> 3) & 1) * 8;
    const int ac = lane >> 4;
    uint32_t aoffs[4];
#pragma unroll
    for (int mt = 0; mt < 4; mt++) {
        int r = wm * 64 + mt * 16 + arl;
        aoffs[mt] = r * 32 + ((ac * 16) ^ (((r >> 2) & 1) * 16));
    }
    uint32_t boffs[2];
#pragma unroll
    for (int p = 0; p < 2; p++) {
        int g = lane >> 3;
        int n = wn * 32 + p * 16 + (g >> 1) * 8 + (lane & 7);
        int c = g & 1;
        boffs[p] = n * 32 + ((c * 16) ^ (((n >> 2) & 1) * 16));
    }

    auto issue = [&](int s, int k0) {
        uint32_t d = sbase + s * ST3_BYTES + dsto;
        CP_ASYNC16(d,          Ahi + gA + k0);
        CP_ASYNC16(d + 4096u,  Alo + gA + k0);
        CP_ASYNC16(d + 8192u,  Bhi + gB + k0);
        CP_ASYNC16(d + 12288u, Blo + gB + k0);
    };

    issue(0, 0);  CP_COMMIT();
    issue(1, 16); CP_COMMIT();

    for (int ks = 0; ks < 64; ks++) {
        CP_WAIT1();
        __syncthreads();
        int s = ks % 3;
        if (ks < 62) issue((ks + 2) % 3, (ks + 2) * 16);
        CP_COMMIT();

        const uint32_t st = sbase + s * ST3_BYTES;
        uint32_t bh[8], bl[8];
        LDSM4(bh[0], bh[1], bh[2], bh[3], st + 8192u + boffs[0]);
        LDSM4(bh[4], bh[5], bh[6], bh[7], st + 8192u + boffs[1]);
        LDSM4(bl[0], bl[1], bl[2], bl[3], st + 12288u + boffs[0]);
        LDSM4(bl[4], bl[5], bl[6], bl[7], st + 12288u + boffs[1]);
#pragma unroll
        for (int mt = 0; mt < 4; mt++) {
            uint32_t H0, H1, H2, H3, L0, L1, L2, L3;
            LDSM4(H0, H1, H2, H3, st + aoffs[mt]);
#pragma unroll
            for (int nt = 0; nt < 4; nt++)
                MMA16816(acc[mt][nt], H0, H1, H2, H3, bh[nt * 2], bh[nt * 2 + 1]);
#pragma unroll
            for (int nt = 0; nt < 4; nt++)
                MMA16816(acc[mt][nt], H0, H1, H2, H3, bl[nt * 2], bl[nt * 2 + 1]);
            LDSM4(L0, L1, L2, L3, st + 4096u + aoffs[mt]);
#pragma unroll
            for (int nt = 0; nt < 4; nt++)
                MMA16816(acc[mt][nt], L0, L1, L2, L3, bh[nt * 2], bh[nt * 2 + 1]);
        }
    }

#pragma unroll
    for (int mt = 0; mt < 4; mt++)
#pragma unroll
        for (int nt = 0; nt < 4; nt++)
#pragma unroll
            for (int r = 0; r < 4; r++) {
                int m = mtile * 128 + wm * 64 + mt * 16 + gr + 8 * (r >> 1);
                int n = ntile * 128 + wn * 32 + nt * 8 + q * 2 + (r & 1);
                float v = acc[mt][nt][r] + __ldg(bias + n);
                if (SPLIT) {
                    __half h = __float2half_rn(v);
                    ohi[(size_t)m * NC + n] = h;
                    olo[(size_t)m * NC + n] =
                        __float2half_rn(v - __half2float(h));
                } else {
                    outf[(size_t)m * NC + n] = v;
                }
            }
}

// ---------------------------------------------------------------------------
static void* symp(const void* symbol)
{
    void* p = nullptr;
    cudaGetSymbolAddress(&p, symbol);
    return p;
}

extern "C" void kernel_launch(void* const* d_in, const int* in_sizes, int n_in,
                              void* d_out, int out_size)
{
    const float* x0  = (const float*)d_in[0];
    const float* W   = (const float*)d_in[1];
    const float* b   = (const float*)d_in[2];
    const float* W1  = (const float*)d_in[3];
    const float* b1  = (const float*)d_in[4];
    const float* Wm  = (const float*)d_in[5];
    const float* bm  = (const float*)d_in[6];
    const float* Wa  = (const float*)d_in[7];
    const float* ba  = (const float*)d_in[8];
    const float* g1w = (const float*)d_in[9];
    const float* g1b = (const float*)d_in[10];
    const float* g2w = (const float*)d_in[11];
    const float* g2b = (const float*)d_in[12];
    float* out = (float*)d_out;

    __half* p_Xhi  = (__half*)symp(g_Xhi);
    __half* p_Whi  = (__half*)symp(g_Whi);
    __half* p_Wlo  = (__half*)symp(g_Wlo);
    __half* p_W1hi = (__half*)symp(g_W1hi);
    __half* p_W1lo = (__half*)symp(g_W1lo);
    __half* p_xghi = (__half*)symp(g_xghi);
    __half* p_xglo = (__half*)symp(g_xglo);
    __half* p_yhi  = (__half*)symp(g_yhi);
    __half* p_ylo  = (__half*)symp(g_ylo);
    float* p_colmean = (float*)symp(g_colmean);
    float* p_xmean = (float*)symp(g_xmean);
    float* p_xA    = (float*)symp(g_xA);
    float* p_tM    = (float*)symp(g_tM);
    float* p_tA    = (float*)symp(g_tA);
    float* p_gn1   = (float*)symp(g_gn1);
    float* p_gn2   = (float*)symp(g_gn2);
    float* p_v     = (float*)symp(g_v);
    float* p_u     = (float*)symp(g_u);

    // 0) splits
    split_colsum<<<NB * 128, 256>>>(x0, p_Xhi);
    wsplit<<<(NC * NC / 4) / 256, 256>>>(W, p_Whi, p_Wlo);
    wsplit<<<(NC * NC / 4) / 256, 256>>>(W1, p_W1hi, p_W1lo);
    colmean_reduce<<<(NB * NC) / 256, 256>>>();

    // 1) approx GEMM1 + candidate reduce + exact max recompute
    dim3 g1(8, 512);
    gemm1_mma<<<g1, 256>>>(p_Xhi, p_Whi);
    reduce_cand<<<(NB * NC) / 256, 256>>>();
    dim3 gex(NC / 8, NB);
    exact_max<<<gex, 256>>>(x0, W, b);

    // 2) exact mean path + pooled branches + GroupNorm
    dim3 gst(NC / 8, NB);
    small_gemm_T<<<gst, 256>>>(p_colmean, W, b, p_xmean);
    dim3 gst2(NC / 8, NB, 2);
    small_gemm_T2<<<gst2, 256>>>(p_xmean, Wm, bm, p_tM, p_xA, Wa, ba, p_tA);
    dim3 ggn(NB, 2);
    gn_kernel2<<<ggn, 1024>>>(p_tM, g1w, g1b, p_gn1, p_tA, g2w, g2b, p_gn2);

    // 3) u = W^T(W1^T(gn1+gn2))
    dim3 gsn(NC / 256, NB);
    small_gemm_N<<<gsn, 256>>>(p_gn1, p_gn2, W1, p_v);
    small_gemm_N<<<gsn, 256>>>(p_v, (const float*)nullptr, W, p_u);

    // 4) scores, 5) top-k + gather, 6) fp16x3 recompute of selected rows
    dim3 gdot(NL / 8, NB);
    dot_kernel<<<gdot, 256>>>(x0);
    topk_kernel<<<NB, 256>>>();
    gather_kernel<<<NB * KSEL, 256>>>(x0);
    dim3 gg2(8, (NB * KSEL) / 128);
    gemm_x3<1><<<gg2, 256>>>(p_xghi, p_xglo, p_Whi, p_Wlo, b,
                             nullptr, p_yhi, p_ylo);
    gemm_x3<0><<<gg2, 256>>>(p_yhi, p_ylo, p_W1hi, p_W1lo, b1,
                             out, nullptr, nullptr);
}